// round 1
// baseline (speedup 1.0000x reference)
#include <cuda_runtime.h>

// Problem constants
#define S_  512
#define B_  64
#define T_  768
#define A_  512
#define H1_ 768
#define H2_ 640
#define M_  (S_*B_)   // 32768 rows (s-major, b-minor), row length T_

// Scratch (allocation-free rule: __device__ globals)
__device__ float g_c1[B_*H1_];   // text @ W11[T:] + b11   [b][h]
__device__ float g_c2[B_*H2_];   // anp  @ W12[T:] + b12   [b][h]
__device__ float g_s [2*M_];     // pre-softmax scores, seg-major  [seg][s*B+b]
__device__ float g_w [M_];       // combined softmax weights       [s*B+b]

// ---------------------------------------------------------------------------
// Zero the score accumulators (they are built with atomicAdd)
__global__ void zero_s_kernel() {
    int i = blockIdx.x * blockDim.x + threadIdx.x;
    if (i < 2*M_) g_s[i] = 0.f;
}

// ---------------------------------------------------------------------------
// Per-batch bias vectors: c1 = text @ W11[T:] + b11, c2 = anp @ W12[T:] + b12
__global__ void precompute_c_kernel(const float* __restrict__ text,
                                    const float* __restrict__ anp,
                                    const float* __restrict__ W11,
                                    const float* __restrict__ b11,
                                    const float* __restrict__ W12,
                                    const float* __restrict__ b12) {
    int idx = blockIdx.x * blockDim.x + threadIdx.x;
    if (idx < B_*H1_) {
        int b = idx / H1_, h = idx - b*H1_;
        const float* Wl = W11 + (long long)T_*H1_;   // rows T..2T-1
        const float* tr = text + b*T_;
        float acc = b11[h];
        #pragma unroll 4
        for (int k = 0; k < T_; k++) acc = fmaf(tr[k], Wl[(long long)k*H1_ + h], acc);
        g_c1[idx] = acc;
    } else {
        int j = idx - B_*H1_;
        if (j >= B_*H2_) return;
        int b = j / H2_, h = j - b*H2_;
        const float* Wl = W12 + (long long)T_*H2_;   // rows T..T+A-1
        const float* ar = anp + b*A_;
        float acc = b12[h];
        #pragma unroll 4
        for (int k = 0; k < A_; k++) acc = fmaf(ar[k], Wl[(long long)k*H2_ + h], acc);
        g_c2[j] = acc;
    }
}

// ---------------------------------------------------------------------------
// Fused heavy GEMM:
//   for each row m=(s,b), each hidden col n:
//     u = (text_seq[m,:] . W[:,n]) + c[b,n];  score[m] += tanh(u) * W2[n]
// 128x128x8 SGEMM tiles, 256 threads, 8x8 per-thread microtile,
// register-prefetch double buffering, epilogue fused (tanh + dot + atomic).
#define BM 128
#define BN 128
#define BK 8

__global__ __launch_bounds__(256)
void fused_score_kernel(const float* __restrict__ Amat,   // text_seq (M_, T_)
                        const float* __restrict__ W11,
                        const float* __restrict__ W12,
                        const float* __restrict__ W21,
                        const float* __restrict__ W22) {
    __shared__ float As[BK][BM];
    __shared__ float Bs[BK][BN];

    // gridDim = (11, M_/BM): x = N-tile (fastest varying -> blocks sharing an
    // A-tile are scheduled concurrently and reuse it through L2)
    const int nt  = blockIdx.x;              // 0..10
    const int seg = (nt >= H1_/BN) ? 1 : 0;  // 0: W11/H1, 1: W12/H2
    const int n0  = seg ? (nt - H1_/BN)*BN : nt*BN;
    const int Nseg = seg ? H2_ : H1_;
    const float* Bmat  = seg ? W12  : W11;   // top T_ rows are the text part
    const float* W2    = seg ? W22  : W21;
    const float* cbase = seg ? g_c2 : g_c1;
    const int m0 = blockIdx.y * BM;

    const int tid = threadIdx.x;
    const int tx  = tid & 15;      // 16 col-groups
    const int ty  = tid >> 4;      // 16 row-groups

    // global->smem load assignments
    const int arow = tid >> 1;             // 0..127
    const int acol = (tid & 1) * 4;        // 0 or 4
    const int brow = tid >> 5;             // 0..7
    const int bcol = (tid & 31) * 4;       // 0..124

    const float* Aptr = Amat + (long long)(m0 + arow) * T_ + acol;
    const float* Bptr = Bmat + (long long)brow * Nseg + n0 + bcol;

    float acc[8][8];
    #pragma unroll
    for (int i = 0; i < 8; i++)
        #pragma unroll
        for (int j = 0; j < 8; j++) acc[i][j] = 0.f;

    // prologue: tile k0=0
    {
        float4 a = *(const float4*)Aptr;
        float4 b = *(const float4*)Bptr;
        As[acol+0][arow] = a.x; As[acol+1][arow] = a.y;
        As[acol+2][arow] = a.z; As[acol+3][arow] = a.w;
        *(float4*)&Bs[brow][bcol] = b;
    }
    __syncthreads();

    for (int k0 = 0; k0 < T_; k0 += BK) {
        float4 an, bn;
        const bool has = (k0 + BK) < T_;
        if (has) {  // prefetch next K-tile into registers (overlaps compute)
            an = *(const float4*)(Aptr + (k0 + BK));
            bn = *(const float4*)(Bptr + (long long)(k0 + BK) * Nseg);
        }
        #pragma unroll
        for (int kk = 0; kk < BK; kk++) {
            float af[8], bf[8];
            #pragma unroll
            for (int i = 0; i < 8; i++) af[i] = As[kk][ty*8 + i];
            #pragma unroll
            for (int j = 0; j < 8; j++) bf[j] = Bs[kk][tx*8 + j];
            #pragma unroll
            for (int i = 0; i < 8; i++)
                #pragma unroll
                for (int j = 0; j < 8; j++)
                    acc[i][j] = fmaf(af[i], bf[j], acc[i][j]);
        }
        __syncthreads();
        if (has) {
            As[acol+0][arow] = an.x; As[acol+1][arow] = an.y;
            As[acol+2][arow] = an.z; As[acol+3][arow] = an.w;
            *(float4*)&Bs[brow][bcol] = bn;
        }
        __syncthreads();
    }

    // Epilogue: u = acc + c[b][n]; p = sum_n tanh(u)*W2[n]; atomic into g_s
    float w2v[8];
    #pragma unroll
    for (int j = 0; j < 8; j++) w2v[j] = W2[n0 + tx*8 + j];

    const int lane = tid & 31;
    #pragma unroll
    for (int i = 0; i < 8; i++) {
        const int r = ty*8 + i;
        const int b = (m0 + r) & (B_ - 1);     // m = s*B + b, B=64
        const float* crow = cbase + (long long)b * Nseg + n0 + tx*8;
        float p = 0.f;
        #pragma unroll
        for (int j = 0; j < 8; j++) {
            float u = acc[i][j] + crow[j];
            p += tanhf(u) * w2v[j];
        }
        // reduce across the 16 tx-lanes sharing this row (contiguous half-warp)
        p += __shfl_xor_sync(0xffffffffu, p, 1);
        p += __shfl_xor_sync(0xffffffffu, p, 2);
        p += __shfl_xor_sync(0xffffffffu, p, 4);
        p += __shfl_xor_sync(0xffffffffu, p, 8);
        if ((lane & 15) == 0)
            atomicAdd(&g_s[seg*M_ + m0 + r], p);
    }
}

// ---------------------------------------------------------------------------
// Softmax over S per batch column for both branches; combine into one weight.
// (b21/b22 dropped: softmax is shift-invariant.)
__global__ void softmax_combine_kernel() {
    __shared__ float red[S_];
    const int b = blockIdx.x;
    const int s = threadIdx.x;      // 512 threads

    float v1 = g_s[s*B_ + b];
    float v2 = g_s[M_ + s*B_ + b];

    // branch 1 softmax
    red[s] = v1; __syncthreads();
    for (int off = S_/2; off > 0; off >>= 1) {
        if (s < off) red[s] = fmaxf(red[s], red[s+off]);
        __syncthreads();
    }
    float m1 = red[0]; __syncthreads();
    float e1 = expf(v1 - m1);
    red[s] = e1; __syncthreads();
    for (int off = S_/2; off > 0; off >>= 1) {
        if (s < off) red[s] += red[s+off];
        __syncthreads();
    }
    float sum1 = red[0]; __syncthreads();

    // branch 2 softmax
    red[s] = v2; __syncthreads();
    for (int off = S_/2; off > 0; off >>= 1) {
        if (s < off) red[s] = fmaxf(red[s], red[s+off]);
        __syncthreads();
    }
    float m2 = red[0]; __syncthreads();
    float e2 = expf(v2 - m2);
    red[s] = e2; __syncthreads();
    for (int off = S_/2; off > 0; off >>= 1) {
        if (s < off) red[s] += red[s+off];
        __syncthreads();
    }
    float sum2 = red[0];

    g_w[s*B_ + b] = (e1/sum1 + e2/sum2) * (0.5f / (float)S_);
}

// ---------------------------------------------------------------------------
// out[b,t] = sum_s g_w[s,b] * text_seq[s,b,t]
__global__ void weighted_sum_kernel(const float* __restrict__ ts,
                                    float* __restrict__ out) {
    __shared__ float ws[S_];
    const int b = blockIdx.y;
    const int t = blockIdx.x * blockDim.x + threadIdx.x;
    for (int i = threadIdx.x; i < S_; i += blockDim.x) ws[i] = g_w[i*B_ + b];
    __syncthreads();
    float acc = 0.f;
    const float* p = ts + (long long)b * T_ + t;
    #pragma unroll 8
    for (int s = 0; s < S_; s++)
        acc = fmaf(ws[s], p[(long long)s * B_ * T_], acc);
    out[b*T_ + t] = acc;
}

// ---------------------------------------------------------------------------
extern "C" void kernel_launch(void* const* d_in, const int* in_sizes, int n_in,
                              void* d_out, int out_size) {
    const float* text = (const float*)d_in[0];
    const float* anp  = (const float*)d_in[1];
    const float* ts   = (const float*)d_in[2];
    const float* W11  = (const float*)d_in[3];
    const float* b11  = (const float*)d_in[4];
    const float* W21  = (const float*)d_in[5];
    // d_in[6] = b21 (unused: softmax shift-invariant)
    const float* W12  = (const float*)d_in[7];
    const float* b12  = (const float*)d_in[8];
    const float* W22  = (const float*)d_in[9];
    // d_in[10] = b22 (unused)
    (void)in_sizes; (void)n_in; (void)out_size;

    zero_s_kernel<<<(2*M_ + 255)/256, 256>>>();
    precompute_c_kernel<<<(B_*H1_ + B_*H2_ + 255)/256, 256>>>(
        text, anp, W11, b11, W12, b12);

    dim3 g1(H1_/BN + H2_/BN, M_/BM);   // (11, 256), N-tiles fastest
    fused_score_kernel<<<g1, 256>>>(ts, W11, W12, W21, W22);

    softmax_combine_kernel<<<B_, S_>>>();

    dim3 g2(T_/256, B_);
    weighted_sum_kernel<<<g2, 256>>>(ts, (float*)d_out);
}

// round 5
// speedup vs baseline: 4.0275x; 4.0275x over previous
#include <cuda_runtime.h>
#include <cuda_fp16.h>
#include <cstdint>

// ---------------- problem constants ----------------
#define S_   512
#define B_   64
#define T_   768
#define A_   512
#define H1_  768
#define H2_  640
#define M_   (S_*B_)     // 32768
#define NTOT 1408        // H1+H2 = 11 * 128, no padding needed

// ---------------- GEMM tiling ----------------
#define BM   128
#define BN   128
#define BK   64
#define NKS  (T_/BK)     // 12 K-stages
#define STG  4           // pipeline stages
#define A_STAGE 16384    // 128 x 64 fp16
#define B_STAGE 16384    // 64 x 128 fp16
#define STAGE_BYTES (A_STAGE + B_STAGE)
#define SMEM_DYN (STG*STAGE_BYTES)   // 128 KB

// ---------------- device scratch (allocation-free rule) ----------------
__device__ __align__(16) __half g_Ah[(size_t)M_*T_];   // text_seq fp16 [m][k]
__device__ __align__(16) __half g_Bh[(size_t)T_*NTOT]; // W11|W12 fp16  [k][n]
__device__ float g_c [B_*NTOT];    // per-batch bias [b][n]
__device__ float g_W2[NTOT];       // W21|W22
__device__ float g_s [2*M_];       // pre-softmax scores per branch
__device__ float g_w [M_];         // combined softmax weights

// ---------------- helpers ----------------
__device__ __forceinline__ uint32_t s2u(const void* p) {
    return (uint32_t)__cvta_generic_to_shared(p);
}
// A tile: rows of 128B -> XOR bits[6:4] with bits[9:7]
#define SWZA(o) ((o) ^ (((o) >> 3) & 0x70))
// B tile: rows of 256B -> XOR bits[6:4] with bits[10:8]
#define SWZB(o) ((o) ^ ((((o) >> 8) & 7) << 4))

__device__ __forceinline__ void cp16(uint32_t d, const void* s) {
    asm volatile("cp.async.cg.shared.global [%0], [%1], 16;" :: "r"(d), "l"(s) : "memory");
}
#define CP_COMMIT() asm volatile("cp.async.commit_group;" ::: "memory")
#define CP_WAIT2()  asm volatile("cp.async.wait_group 2;" ::: "memory")

#define LDSM_X4(R, addr) \
    asm volatile("ldmatrix.sync.aligned.m8n8.x4.shared.b16 {%0,%1,%2,%3}, [%4];" \
        : "=r"((R)[0]), "=r"((R)[1]), "=r"((R)[2]), "=r"((R)[3]) : "r"(addr))

#define LDSM_X4T(R0, R1, R2, R3, addr) \
    asm volatile("ldmatrix.sync.aligned.m8n8.x4.trans.shared.b16 {%0,%1,%2,%3}, [%4];" \
        : "=r"(R0), "=r"(R1), "=r"(R2), "=r"(R3) : "r"(addr))

#define MMA16816(C, Af, Bf) \
    asm volatile("mma.sync.aligned.m16n8k16.row.col.f32.f16.f16.f32 " \
        "{%0,%1,%2,%3}, {%4,%5,%6,%7}, {%8,%9}, {%0,%1,%2,%3};" \
        : "+f"((C)[0]), "+f"((C)[1]), "+f"((C)[2]), "+f"((C)[3]) \
        : "r"((Af)[0]), "r"((Af)[1]), "r"((Af)[2]), "r"((Af)[3]), \
          "r"((Bf)[0]), "r"((Bf)[1]))

// ---------------------------------------------------------------------------
__global__ void init_misc_kernel(const float* __restrict__ W21,
                                 const float* __restrict__ W22) {
    int i = blockIdx.x * blockDim.x + threadIdx.x;
    if (i < 2*M_) g_s[i] = 0.f;
    if (i < NTOT) g_W2[i] = (i < H1_) ? W21[i] : W22[i - H1_];
}

// text_seq fp32 -> fp16 (vectorized float4 -> 4x half)
__global__ void convert_A_kernel(const float* __restrict__ ts) {
    size_t i = (size_t)blockIdx.x * blockDim.x + threadIdx.x;
    if (i >= (size_t)M_*T_/4) return;
    float4 v = ((const float4*)ts)[i];
    union { __half2 h[2]; uint2 u; } t;
    t.h[0] = __floats2half2_rn(v.x, v.y);
    t.h[1] = __floats2half2_rn(v.z, v.w);
    ((uint2*)g_Ah)[i] = t.u;
}

// Build g_Bh[k][n] = fp16(W11[k][n] for n<768 else W12[k][n-768])
__global__ void convert_B_kernel(const float* __restrict__ W11,
                                 const float* __restrict__ W12) {
    int i = blockIdx.x * blockDim.x + threadIdx.x;
    if (i >= T_*NTOT/4) return;
    int k  = i / (NTOT/4);
    int n4 = (i % (NTOT/4)) * 4;
    float4 v;
    if (n4 < H1_) v = *(const float4*)(W11 + (size_t)k*H1_ + n4);
    else          v = *(const float4*)(W12 + (size_t)k*H2_ + (n4 - H1_));
    union { __half2 h[2]; uint2 u; } t;
    t.h[0] = __floats2half2_rn(v.x, v.y);
    t.h[1] = __floats2half2_rn(v.z, v.w);
    ((uint2*)g_Bh)[i] = t.u;
}

// per-batch bias: c[b][n] = text@W11[T:]+b11 (n<768) | anp@W12[T:]+b12
__global__ void precompute_c_kernel(const float* __restrict__ text,
                                    const float* __restrict__ anp,
                                    const float* __restrict__ W11,
                                    const float* __restrict__ b11,
                                    const float* __restrict__ W12,
                                    const float* __restrict__ b12) {
    int idx = blockIdx.x * blockDim.x + threadIdx.x;
    if (idx >= B_*NTOT) return;
    int b = idx / NTOT, n = idx - b*NTOT;
    float acc;
    if (n < H1_) {
        const float* Wl = W11 + (size_t)T_*H1_;
        const float* tr = text + b*T_;
        acc = b11[n];
        #pragma unroll 4
        for (int k = 0; k < T_; k++) acc = fmaf(tr[k], Wl[(size_t)k*H1_ + n], acc);
    } else {
        int h = n - H1_;
        const float* Wl = W12 + (size_t)T_*H2_;
        const float* ar = anp + b*A_;
        acc = b12[h];
        #pragma unroll 4
        for (int k = 0; k < A_; k++) acc = fmaf(ar[k], Wl[(size_t)k*H2_ + h], acc);
    }
    g_c[idx] = acc;
}

// ---------------------------------------------------------------------------
// Fused fp16 mma.sync GEMM + bias + tanh + W2-dot + score accumulation.
// CTA tile 128(M) x 128(N) x 768(K); 8 warps as 4(M) x 2(N), warp tile 32x64.
__global__ __launch_bounds__(256, 1)
void fused_score_mma() {
    extern __shared__ __align__(1024) char smem[];
    const uint32_t sb = s2u(smem);
    const int tid  = threadIdx.x;
    const int lane = tid & 31;
    const int wid  = tid >> 5;
    const int warp_m = wid & 3;    // 0..3  -> m offset 32*warp_m
    const int warp_n = wid >> 2;   // 0..1  -> n offset 64*warp_n

    const int n0 = blockIdx.x * BN;   // 0..1280 (x fastest: N tiles share A via L2)
    const int m0 = blockIdx.y * BM;
    const int seg = (n0 >= H1_) ? 1 : 0;

    float cr[2][8][4];
    #pragma unroll
    for (int mi = 0; mi < 2; mi++)
        #pragma unroll
        for (int ni = 0; ni < 8; ni++)
            #pragma unroll
            for (int r = 0; r < 4; r++) cr[mi][ni][r] = 0.f;

    // stage loader: A tile [128 m][64 k] fp16 (128B rows, SWZA);
    //               B tile [64 k][128 n] fp16 (256B rows, SWZB)
    auto load_stage = [&](int buf, int ks) {
        const uint32_t sA = sb + buf*STAGE_BYTES;
        const uint32_t sB = sA + A_STAGE;
        #pragma unroll
        for (int j = 0; j < 4; j++) {
            int i = tid + 256*j;
            int row = i >> 3, c8 = i & 7;
            cp16(sA + SWZA(row*128 + c8*16),
                 g_Ah + (size_t)(m0 + row)*T_ + ks*BK + c8*8);
        }
        #pragma unroll
        for (int j = 0; j < 4; j++) {
            int i = tid + 256*j;
            int k = i >> 4, n16 = i & 15;
            cp16(sB + SWZB(k*256 + n16*16),
                 g_Bh + (size_t)(ks*BK + k)*NTOT + n0 + n16*8);
        }
    };

    auto compute_stage = [&](int buf) {
        const uint32_t sA = sb + buf*STAGE_BYTES;
        const uint32_t sB = sA + A_STAGE;
        #pragma unroll
        for (int kk = 0; kk < 4; kk++) {            // four k16 steps
            uint32_t af[2][4];
            #pragma unroll
            for (int mi = 0; mi < 2; mi++) {
                int m_l = warp_m*32 + mi*16 + (lane & 15);
                int kc  = kk*16 + (lane >> 4)*8;
                LDSM_X4(af[mi], sA + SWZA(m_l*128 + kc*2));
            }
            uint32_t bf[8][2];
            #pragma unroll
            for (int nj = 0; nj < 4; nj++) {
                int k = kk*16 + ((lane >> 3) & 1)*8 + (lane & 7);
                int n = warp_n*64 + nj*16 + (lane >> 4)*8;
                uint32_t r0, r1, r2, r3;
                LDSM_X4T(r0, r1, r2, r3, sB + SWZB(k*256 + n*2));
                bf[nj*2  ][0] = r0; bf[nj*2  ][1] = r1;
                bf[nj*2+1][0] = r2; bf[nj*2+1][1] = r3;
            }
            #pragma unroll
            for (int mi = 0; mi < 2; mi++)
                #pragma unroll
                for (int ni = 0; ni < 8; ni++)
                    MMA16816(cr[mi][ni], af[mi], bf[ni]);
        }
    };

    // prologue: stages 0..2
    #pragma unroll
    for (int s = 0; s < STG-1; s++) { load_stage(s, s); CP_COMMIT(); }

    #pragma unroll 1
    for (int ks = 0; ks < NKS; ks++) {
        CP_WAIT2();
        __syncthreads();
        int ld = ks + STG - 1;
        if (ld < NKS) load_stage(ld % STG, ld);
        CP_COMMIT();
        compute_stage(ks % STG);
    }

    // ---- epilogue: stage bias tile + W2 in smem (reuse pipeline smem) ----
    __syncthreads();
    float* c_s  = (float*)smem;            // [64][128]
    float* w2_s = c_s + 64*128;
    for (int i = tid; i < 64*128; i += 256) {
        int b = i >> 7, n = i & 127;
        c_s[i] = g_c[b*NTOT + n0 + n];
    }
    if (tid < 128) w2_s[tid] = g_W2[n0 + tid];
    __syncthreads();

    // thread element map: row = warp_m*32 + mi*16 + half*8 + lane/4
    //                     col = warp_n*64 + ni*8 + (lane%4)*2 (+1)
    float p[4];
    #pragma unroll
    for (int mi = 0; mi < 2; mi++) {
        #pragma unroll
        for (int hf = 0; hf < 2; hf++) {
            int r  = warp_m*32 + mi*16 + hf*8 + (lane >> 2);
            int bb = r & 63;                       // m0 is a multiple of 128
            const float* crow = c_s + bb*128;
            float acc = 0.f;
            #pragma unroll
            for (int ni = 0; ni < 8; ni++) {
                int cc = warp_n*64 + ni*8 + (lane & 3)*2;
                float u0 = cr[mi][ni][hf*2+0] + crow[cc];
                float u1 = cr[mi][ni][hf*2+1] + crow[cc+1];
                acc += tanhf(u0)*w2_s[cc] + tanhf(u1)*w2_s[cc+1];
            }
            p[mi*2 + hf] = acc;
        }
    }
    #pragma unroll
    for (int i = 0; i < 4; i++) {
        p[i] += __shfl_xor_sync(0xffffffffu, p[i], 1);
        p[i] += __shfl_xor_sync(0xffffffffu, p[i], 2);
    }
    if ((lane & 3) == 0) {
        #pragma unroll
        for (int mi = 0; mi < 2; mi++)
            #pragma unroll
            for (int hf = 0; hf < 2; hf++) {
                int r = warp_m*32 + mi*16 + hf*8 + (lane >> 2);
                atomicAdd(&g_s[seg*M_ + m0 + r], p[mi*2 + hf]);
            }
    }
}

// ---------------------------------------------------------------------------
// softmax over S per batch for both branches; combine. (b21/b22 shift-invariant)
__global__ void softmax_combine_kernel() {
    __shared__ float red[S_];
    const int b = blockIdx.x;
    const int s = threadIdx.x;

    float v1 = g_s[s*B_ + b];
    float v2 = g_s[M_ + s*B_ + b];

    red[s] = v1; __syncthreads();
    for (int off = S_/2; off > 0; off >>= 1) {
        if (s < off) red[s] = fmaxf(red[s], red[s+off]);
        __syncthreads();
    }
    float m1 = red[0]; __syncthreads();
    float e1 = expf(v1 - m1);
    red[s] = e1; __syncthreads();
    for (int off = S_/2; off > 0; off >>= 1) {
        if (s < off) red[s] += red[s+off];
        __syncthreads();
    }
    float sum1 = red[0]; __syncthreads();

    red[s] = v2; __syncthreads();
    for (int off = S_/2; off > 0; off >>= 1) {
        if (s < off) red[s] = fmaxf(red[s], red[s+off]);
        __syncthreads();
    }
    float m2 = red[0]; __syncthreads();
    float e2 = expf(v2 - m2);
    red[s] = e2; __syncthreads();
    for (int off = S_/2; off > 0; off >>= 1) {
        if (s < off) red[s] += red[s+off];
        __syncthreads();
    }
    float sum2 = red[0];

    g_w[s*B_ + b] = (e1/sum1 + e2/sum2) * (0.5f / (float)S_);
}

// ---------------------------------------------------------------------------
// out[b,t] = sum_s g_w[s,b] * text_seq[s,b,t]
__global__ void weighted_sum_kernel(const float* __restrict__ ts,
                                    float* __restrict__ out) {
    __shared__ float ws[S_];
    const int b = blockIdx.y;
    const int t = blockIdx.x * blockDim.x + threadIdx.x;
    for (int i = threadIdx.x; i < S_; i += blockDim.x) ws[i] = g_w[i*B_ + b];
    __syncthreads();
    float acc = 0.f;
    const float* p = ts + (size_t)b * T_ + t;
    #pragma unroll 8
    for (int s = 0; s < S_; s++)
        acc = fmaf(ws[s], p[(size_t)s * B_ * T_], acc);
    out[b*T_ + t] = acc;
}

// ---------------------------------------------------------------------------
extern "C" void kernel_launch(void* const* d_in, const int* in_sizes, int n_in,
                              void* d_out, int out_size) {
    const float* text = (const float*)d_in[0];
    const float* anp  = (const float*)d_in[1];
    const float* ts   = (const float*)d_in[2];
    const float* W11  = (const float*)d_in[3];
    const float* b11  = (const float*)d_in[4];
    const float* W21  = (const float*)d_in[5];
    // d_in[6] = b21 (softmax shift-invariant -> unused)
    const float* W12  = (const float*)d_in[7];
    const float* b12  = (const float*)d_in[8];
    const float* W22  = (const float*)d_in[9];
    // d_in[10] = b22 (unused)
    (void)in_sizes; (void)n_in; (void)out_size;

    cudaFuncSetAttribute(fused_score_mma,
                         cudaFuncAttributeMaxDynamicSharedMemorySize, SMEM_DYN);

    init_misc_kernel<<<(2*M_ + 255)/256, 256>>>(W21, W22);
    convert_A_kernel<<<(int)(((size_t)M_*T_/4 + 255)/256), 256>>>(ts);
    convert_B_kernel<<<(T_*NTOT/4 + 255)/256, 256>>>(W11, W12);
    precompute_c_kernel<<<(B_*NTOT + 255)/256, 256>>>(text, anp, W11, b11, W12, b12);

    dim3 g1(NTOT/BN, M_/BM);   // (11, 256), N-tiles fastest -> A reuse in L2
    fused_score_mma<<<g1, 256, SMEM_DYN>>>();

    softmax_combine_kernel<<<B_, S_>>>();

    dim3 g2(T_/256, B_);
    weighted_sum_kernel<<<g2, 256>>>(ts, (float*)d_out);
}

// round 6
// speedup vs baseline: 6.1942x; 1.5380x over previous
#include <cuda_runtime.h>
#include <cuda_fp16.h>
#include <cstdint>

// ---------------- problem constants ----------------
#define S_   512
#define B_   64
#define T_   768
#define A_   512
#define H1_  768
#define H2_  640
#define M_   (S_*B_)     // 32768
#define NTOT 1408        // H1+H2 = 11 * 128

// ---------------- GEMM tiling ----------------
#define BM   128
#define BN   128
#define BK   64
#define NKS  (T_/BK)     // 12 K-stages
#define STG  3           // pipeline stages (96KB smem -> 2 CTAs/SM)
#define A_STAGE 16384    // 128 x 64 fp16
#define B_STAGE 16384    // 64 x 128 fp16
#define STAGE_BYTES (A_STAGE + B_STAGE)
#define SMEM_DYN (STG*STAGE_BYTES)   // 96 KB

#define KSPLIT 8         // precompute_c split-K factor
#define SSPLIT 4         // weighted_sum split-S factor

// ---------------- device scratch (allocation-free rule) ----------------
__device__ __align__(16) __half g_Ah[(size_t)M_*T_];   // text_seq fp16 [m][k]
__device__ __align__(16) __half g_Bh[(size_t)T_*NTOT]; // W11|W12 fp16  [k][n]
__device__ float g_c [B_*NTOT];    // per-batch bias [b][n]
__device__ float g_W2[NTOT];       // W21|W22
__device__ float g_s [2*M_];       // pre-softmax scores per branch
__device__ float g_w [M_];         // combined softmax weights

// ---------------- helpers ----------------
__device__ __forceinline__ uint32_t s2u(const void* p) {
    return (uint32_t)__cvta_generic_to_shared(p);
}
// A tile: rows of 128B -> XOR bits[6:4] with bits[9:7]
#define SWZA(o) ((o) ^ (((o) >> 3) & 0x70))
// B tile: rows of 256B -> XOR bits[6:4] with bits[10:8]
#define SWZB(o) ((o) ^ ((((o) >> 8) & 7) << 4))

__device__ __forceinline__ void cp16(uint32_t d, const void* s) {
    asm volatile("cp.async.cg.shared.global [%0], [%1], 16;" :: "r"(d), "l"(s) : "memory");
}
#define CP_COMMIT() asm volatile("cp.async.commit_group;" ::: "memory")
#define CP_WAIT1()  asm volatile("cp.async.wait_group 1;" ::: "memory")

#define LDSM_X4(R, addr) \
    asm volatile("ldmatrix.sync.aligned.m8n8.x4.shared.b16 {%0,%1,%2,%3}, [%4];" \
        : "=r"((R)[0]), "=r"((R)[1]), "=r"((R)[2]), "=r"((R)[3]) : "r"(addr))

#define LDSM_X4T(R0, R1, R2, R3, addr) \
    asm volatile("ldmatrix.sync.aligned.m8n8.x4.trans.shared.b16 {%0,%1,%2,%3}, [%4];" \
        : "=r"(R0), "=r"(R1), "=r"(R2), "=r"(R3) : "r"(addr))

#define MMA16816(C, Af, Bf) \
    asm volatile("mma.sync.aligned.m16n8k16.row.col.f32.f16.f16.f32 " \
        "{%0,%1,%2,%3}, {%4,%5,%6,%7}, {%8,%9}, {%0,%1,%2,%3};" \
        : "+f"((C)[0]), "+f"((C)[1]), "+f"((C)[2]), "+f"((C)[3]) \
        : "r"((Af)[0]), "r"((Af)[1]), "r"((Af)[2]), "r"((Af)[3]), \
          "r"((Bf)[0]), "r"((Bf)[1]))

// ---------------------------------------------------------------------------
// zero g_s, g_c, d_out; build combined W2
__global__ void init_misc_kernel(const float* __restrict__ W21,
                                 const float* __restrict__ W22,
                                 float* __restrict__ out) {
    int i = blockIdx.x * blockDim.x + threadIdx.x;
    if (i < 2*M_)    g_s[i] = 0.f;
    if (i < B_*NTOT) g_c[i] = 0.f;
    if (i < B_*T_)   out[i] = 0.f;
    if (i < NTOT)    g_W2[i] = (i < H1_) ? W21[i] : W22[i - H1_];
}

// text_seq fp32 -> fp16 (vectorized)
__global__ void convert_A_kernel(const float* __restrict__ ts) {
    size_t i = (size_t)blockIdx.x * blockDim.x + threadIdx.x;
    if (i >= (size_t)M_*T_/4) return;
    float4 v = ((const float4*)ts)[i];
    union { __half2 h[2]; uint2 u; } t;
    t.h[0] = __floats2half2_rn(v.x, v.y);
    t.h[1] = __floats2half2_rn(v.z, v.w);
    ((uint2*)g_Ah)[i] = t.u;
}

// g_Bh[k][n] = fp16(W11[k][n] for n<768 else W12[k][n-768])
__global__ void convert_B_kernel(const float* __restrict__ W11,
                                 const float* __restrict__ W12) {
    int i = blockIdx.x * blockDim.x + threadIdx.x;
    if (i >= T_*NTOT/4) return;
    int k  = i / (NTOT/4);
    int n4 = (i % (NTOT/4)) * 4;
    float4 v;
    if (n4 < H1_) v = *(const float4*)(W11 + (size_t)k*H1_ + n4);
    else          v = *(const float4*)(W12 + (size_t)k*H2_ + (n4 - H1_));
    union { __half2 h[2]; uint2 u; } t;
    t.h[0] = __floats2half2_rn(v.x, v.y);
    t.h[1] = __floats2half2_rn(v.z, v.w);
    ((uint2*)g_Bh)[i] = t.u;
}

// per-batch bias (split-K x8, atomic accumulate into zeroed g_c):
// c[b][n] = text@W11[T:]+b11 (n<768) | anp@W12[T:]+b12
__global__ void precompute_c_kernel(const float* __restrict__ text,
                                    const float* __restrict__ anp,
                                    const float* __restrict__ W11,
                                    const float* __restrict__ b11,
                                    const float* __restrict__ W12,
                                    const float* __restrict__ b12) {
    int idx = blockIdx.x * blockDim.x + threadIdx.x;
    if (idx >= KSPLIT*B_*NTOT) return;
    int sp = idx / (B_*NTOT);
    int r  = idx - sp*(B_*NTOT);
    int b  = r / NTOT, n = r - b*NTOT;
    float acc = 0.f;
    if (n < H1_) {
        const int kp = T_/KSPLIT;                    // 96
        const float* Wl = W11 + (size_t)(T_ + sp*kp)*H1_;
        const float* tr = text + b*T_ + sp*kp;
        if (sp == 0) acc = b11[n];
        #pragma unroll 4
        for (int k = 0; k < kp; k++) acc = fmaf(tr[k], Wl[(size_t)k*H1_ + n], acc);
    } else {
        int h = n - H1_;
        const int kp = A_/KSPLIT;                    // 64
        const float* Wl = W12 + (size_t)(T_ + sp*kp)*H2_;
        const float* ar = anp + b*A_ + sp*kp;
        if (sp == 0) acc = b12[h];
        #pragma unroll 4
        for (int k = 0; k < kp; k++) acc = fmaf(ar[k], Wl[(size_t)k*H2_ + h], acc);
    }
    atomicAdd(&g_c[r], acc);
}

// ---------------------------------------------------------------------------
// Fused fp16 mma.sync GEMM + bias + tanh + W2-dot + score accumulation.
// CTA tile 128(M) x 128(N) x 768(K); 8 warps as 4(M) x 2(N), warp tile 32x64.
// 96KB smem + <=128 regs -> 2 CTAs/SM for cross-CTA latency hiding.
__global__ __launch_bounds__(256, 2)
void fused_score_mma() {
    extern __shared__ __align__(1024) char smem[];
    const uint32_t sb = s2u(smem);
    const int tid  = threadIdx.x;
    const int lane = tid & 31;
    const int wid  = tid >> 5;
    const int warp_m = wid & 3;    // 0..3  -> m offset 32*warp_m
    const int warp_n = wid >> 2;   // 0..1  -> n offset 64*warp_n

    const int n0 = blockIdx.x * BN;   // x fastest: N tiles share A panel via L2
    const int m0 = blockIdx.y * BM;
    const int seg = (n0 >= H1_) ? 1 : 0;

    float cr[2][8][4];
    #pragma unroll
    for (int mi = 0; mi < 2; mi++)
        #pragma unroll
        for (int ni = 0; ni < 8; ni++)
            #pragma unroll
            for (int r = 0; r < 4; r++) cr[mi][ni][r] = 0.f;

    auto load_stage = [&](int buf, int ks) {
        const uint32_t sA = sb + buf*STAGE_BYTES;
        const uint32_t sB = sA + A_STAGE;
        #pragma unroll
        for (int j = 0; j < 4; j++) {
            int i = tid + 256*j;
            int row = i >> 3, c8 = i & 7;
            cp16(sA + SWZA(row*128 + c8*16),
                 g_Ah + (size_t)(m0 + row)*T_ + ks*BK + c8*8);
        }
        #pragma unroll
        for (int j = 0; j < 4; j++) {
            int i = tid + 256*j;
            int k = i >> 4, n16 = i & 15;
            cp16(sB + SWZB(k*256 + n16*16),
                 g_Bh + (size_t)(ks*BK + k)*NTOT + n0 + n16*8);
        }
    };

    auto compute_stage = [&](int buf) {
        const uint32_t sA = sb + buf*STAGE_BYTES;
        const uint32_t sB = sA + A_STAGE;
        #pragma unroll
        for (int kk = 0; kk < 4; kk++) {            // four k16 steps
            uint32_t af[2][4];
            #pragma unroll
            for (int mi = 0; mi < 2; mi++) {
                int m_l = warp_m*32 + mi*16 + (lane & 15);
                int kc  = kk*16 + (lane >> 4)*8;
                LDSM_X4(af[mi], sA + SWZA(m_l*128 + kc*2));
            }
            uint32_t bf[8][2];
            #pragma unroll
            for (int nj = 0; nj < 4; nj++) {
                int k = kk*16 + ((lane >> 3) & 1)*8 + (lane & 7);
                int n = warp_n*64 + nj*16 + (lane >> 4)*8;
                uint32_t r0, r1, r2, r3;
                LDSM_X4T(r0, r1, r2, r3, sB + SWZB(k*256 + n*2));
                bf[nj*2  ][0] = r0; bf[nj*2  ][1] = r1;
                bf[nj*2+1][0] = r2; bf[nj*2+1][1] = r3;
            }
            #pragma unroll
            for (int mi = 0; mi < 2; mi++)
                #pragma unroll
                for (int ni = 0; ni < 8; ni++)
                    MMA16816(cr[mi][ni], af[mi], bf[ni]);
        }
    };

    // prologue: stages 0..1
    #pragma unroll
    for (int s = 0; s < STG-1; s++) { load_stage(s, s); CP_COMMIT(); }

    #pragma unroll 1
    for (int ks = 0; ks < NKS; ks++) {
        CP_WAIT1();
        __syncthreads();
        int ld = ks + STG - 1;
        if (ld < NKS) load_stage(ld % STG, ld);
        CP_COMMIT();
        compute_stage(ks % STG);
    }

    // ---- epilogue: stage bias tile + W2 in smem (reuse pipeline smem) ----
    __syncthreads();
    float* c_s  = (float*)smem;            // [64][128]
    float* w2_s = c_s + 64*128;
    for (int i = tid; i < 64*128; i += 256) {
        int b = i >> 7, n = i & 127;
        c_s[i] = g_c[b*NTOT + n0 + n];
    }
    if (tid < 128) w2_s[tid] = g_W2[n0 + tid];
    __syncthreads();

    float p[4];
    #pragma unroll
    for (int mi = 0; mi < 2; mi++) {
        #pragma unroll
        for (int hf = 0; hf < 2; hf++) {
            int r  = warp_m*32 + mi*16 + hf*8 + (lane >> 2);
            int bb = r & 63;                       // m0 multiple of 128, B=64
            const float* crow = c_s + bb*128;
            float acc = 0.f;
            #pragma unroll
            for (int ni = 0; ni < 8; ni++) {
                int cc = warp_n*64 + ni*8 + (lane & 3)*2;
                float u0 = cr[mi][ni][hf*2+0] + crow[cc];
                float u1 = cr[mi][ni][hf*2+1] + crow[cc+1];
                acc += tanhf(u0)*w2_s[cc] + tanhf(u1)*w2_s[cc+1];
            }
            p[mi*2 + hf] = acc;
        }
    }
    #pragma unroll
    for (int i = 0; i < 4; i++) {
        p[i] += __shfl_xor_sync(0xffffffffu, p[i], 1);
        p[i] += __shfl_xor_sync(0xffffffffu, p[i], 2);
    }
    if ((lane & 3) == 0) {
        #pragma unroll
        for (int mi = 0; mi < 2; mi++)
            #pragma unroll
            for (int hf = 0; hf < 2; hf++) {
                int r = warp_m*32 + mi*16 + hf*8 + (lane >> 2);
                atomicAdd(&g_s[seg*M_ + m0 + r], p[mi*2 + hf]);
            }
    }
}

// ---------------------------------------------------------------------------
// softmax over S per batch for both branches; combine. (b21/b22 shift-invariant)
__global__ void softmax_combine_kernel() {
    __shared__ float red[S_];
    const int b = blockIdx.x;
    const int s = threadIdx.x;

    float v1 = g_s[s*B_ + b];
    float v2 = g_s[M_ + s*B_ + b];

    red[s] = v1; __syncthreads();
    for (int off = S_/2; off > 0; off >>= 1) {
        if (s < off) red[s] = fmaxf(red[s], red[s+off]);
        __syncthreads();
    }
    float m1 = red[0]; __syncthreads();
    float e1 = expf(v1 - m1);
    red[s] = e1; __syncthreads();
    for (int off = S_/2; off > 0; off >>= 1) {
        if (s < off) red[s] += red[s+off];
        __syncthreads();
    }
    float sum1 = red[0]; __syncthreads();

    red[s] = v2; __syncthreads();
    for (int off = S_/2; off > 0; off >>= 1) {
        if (s < off) red[s] = fmaxf(red[s], red[s+off]);
        __syncthreads();
    }
    float m2 = red[0]; __syncthreads();
    float e2 = expf(v2 - m2);
    red[s] = e2; __syncthreads();
    for (int off = S_/2; off > 0; off >>= 1) {
        if (s < off) red[s] += red[s+off];
        __syncthreads();
    }
    float sum2 = red[0];

    g_w[s*B_ + b] = (e1/sum1 + e2/sum2) * (0.5f / (float)S_);
}

// ---------------------------------------------------------------------------
// out[b,t] += sum_{s in chunk} g_w[s,b] * text_seq[s,b,t]   (split-S x4)
__global__ void weighted_sum_kernel(const float* __restrict__ ts,
                                    float* __restrict__ out) {
    __shared__ float ws[S_/SSPLIT];
    const int b  = blockIdx.y;
    const int sz = blockIdx.z;
    const int sbeg = sz * (S_/SSPLIT);
    const int t = blockIdx.x * blockDim.x + threadIdx.x;
    for (int i = threadIdx.x; i < S_/SSPLIT; i += blockDim.x)
        ws[i] = g_w[(sbeg + i)*B_ + b];
    __syncthreads();
    float acc = 0.f;
    const float* p = ts + (size_t)sbeg * B_ * T_ + (size_t)b * T_ + t;
    #pragma unroll 8
    for (int s = 0; s < S_/SSPLIT; s++)
        acc = fmaf(ws[s], p[(size_t)s * B_ * T_], acc);
    atomicAdd(&out[b*T_ + t], acc);
}

// ---------------------------------------------------------------------------
extern "C" void kernel_launch(void* const* d_in, const int* in_sizes, int n_in,
                              void* d_out, int out_size) {
    const float* text = (const float*)d_in[0];
    const float* anp  = (const float*)d_in[1];
    const float* ts   = (const float*)d_in[2];
    const float* W11  = (const float*)d_in[3];
    const float* b11  = (const float*)d_in[4];
    const float* W21  = (const float*)d_in[5];
    // d_in[6] = b21 (softmax shift-invariant -> unused)
    const float* W12  = (const float*)d_in[7];
    const float* b12  = (const float*)d_in[8];
    const float* W22  = (const float*)d_in[9];
    // d_in[10] = b22 (unused)
    (void)in_sizes; (void)n_in; (void)out_size;

    cudaFuncSetAttribute(fused_score_mma,
                         cudaFuncAttributeMaxDynamicSharedMemorySize, SMEM_DYN);

    init_misc_kernel<<<(B_*NTOT + 255)/256, 256>>>(W21, W22, (float*)d_out);
    convert_A_kernel<<<(int)(((size_t)M_*T_/4 + 255)/256), 256>>>(ts);
    convert_B_kernel<<<(T_*NTOT/4 + 255)/256, 256>>>(W11, W12);
    precompute_c_kernel<<<(KSPLIT*B_*NTOT + 255)/256, 256>>>(
        text, anp, W11, b11, W12, b12);

    dim3 g1(NTOT/BN, M_/BM);   // (11, 256), N-tiles fastest -> A reuse in L2
    fused_score_mma<<<g1, 256, SMEM_DYN>>>();

    softmax_combine_kernel<<<B_, S_>>>();

    dim3 g2(T_/256, B_, SSPLIT);
    weighted_sum_kernel<<<g2, 256>>>(ts, (float*)d_out);
}

// round 7
// speedup vs baseline: 6.2858x; 1.0148x over previous
#include <cuda_runtime.h>
#include <cuda_fp16.h>
#include <cstdint>

// ---------------- problem constants ----------------
#define S_   512
#define B_   64
#define T_   768
#define A_   512
#define H1_  768
#define H2_  640
#define M_   (S_*B_)     // 32768
#define NTOT 1408        // H1+H2 = 11 * 128

// ---------------- GEMM tiling ----------------
#define BM   128
#define BN   128
#define BK   64
#define NKS  (T_/BK)     // 12 K-stages
#define STG  3           // pipeline stages (96KB smem -> 2 CTAs/SM)
#define A_STAGE 16384    // 128 x 64 fp16
#define B_STAGE 16384    // 64 x 128 fp16
#define STAGE_BYTES (A_STAGE + B_STAGE)
#define SMEM_DYN (STG*STAGE_BYTES)   // 96 KB

#define KSPL 16          // precompute_c split-K factor
#define SSPLIT 4         // weighted_sum split-S factor

// mega-kernel block ranges
#define PRE_BLOCKS  (11*KSPL)                       // 176
#define CVTB_BLOCKS (T_*NTOT/4/256)                 // 1056
#define CVTA_BLOCKS ((int)((size_t)M_*T_/4/256))    // 24576
#define MEGA_BLOCKS (PRE_BLOCKS + CVTB_BLOCKS + CVTA_BLOCKS)

// ---------------- device scratch (allocation-free rule) ----------------
__device__ __align__(16) __half g_Ah[(size_t)M_*T_];   // text_seq fp16 [m][k]
__device__ __align__(16) __half g_Bh[(size_t)T_*NTOT]; // W11|W12 fp16  [k][n]
__device__ float g_c [B_*NTOT];    // per-batch bias [b][n]
__device__ float g_W2[NTOT];       // W21|W22
__device__ float g_s [2*M_];       // pre-softmax scores [seg][b][s]
__device__ float g_w [M_];         // combined softmax weights [b][s]

// ---------------- helpers ----------------
__device__ __forceinline__ uint32_t s2u(const void* p) {
    return (uint32_t)__cvta_generic_to_shared(p);
}
// A tile: rows of 128B -> XOR bits[6:4] with bits[9:7]
#define SWZA(o) ((o) ^ (((o) >> 3) & 0x70))
// B tile: rows of 256B -> XOR bits[6:4] with bits[10:8]
#define SWZB(o) ((o) ^ ((((o) >> 8) & 7) << 4))

__device__ __forceinline__ void cp16(uint32_t d, const void* s) {
    asm volatile("cp.async.cg.shared.global [%0], [%1], 16;" :: "r"(d), "l"(s) : "memory");
}
#define CP_COMMIT() asm volatile("cp.async.commit_group;" ::: "memory")
#define CP_WAIT1()  asm volatile("cp.async.wait_group 1;" ::: "memory")

#define LDSM_X4(R, addr) \
    asm volatile("ldmatrix.sync.aligned.m8n8.x4.shared.b16 {%0,%1,%2,%3}, [%4];" \
        : "=r"((R)[0]), "=r"((R)[1]), "=r"((R)[2]), "=r"((R)[3]) : "r"(addr))

#define LDSM_X4T(R0, R1, R2, R3, addr) \
    asm volatile("ldmatrix.sync.aligned.m8n8.x4.trans.shared.b16 {%0,%1,%2,%3}, [%4];" \
        : "=r"(R0), "=r"(R1), "=r"(R2), "=r"(R3) : "r"(addr))

#define MMA16816(C, Af, Bf) \
    asm volatile("mma.sync.aligned.m16n8k16.row.col.f32.f16.f16.f32 " \
        "{%0,%1,%2,%3}, {%4,%5,%6,%7}, {%8,%9}, {%0,%1,%2,%3};" \
        : "+f"((C)[0]), "+f"((C)[1]), "+f"((C)[2]), "+f"((C)[3]) \
        : "r"((Af)[0]), "r"((Af)[1]), "r"((Af)[2]), "r"((Af)[3]), \
          "r"((Bf)[0]), "r"((Bf)[1]))

// ---------------------------------------------------------------------------
// init: zero g_s and d_out; seed g_c with the bias vectors; build combined W2
__global__ void init_misc_kernel(const float* __restrict__ b11,
                                 const float* __restrict__ b12,
                                 const float* __restrict__ W21,
                                 const float* __restrict__ W22,
                                 float* __restrict__ out) {
    int i = blockIdx.x * blockDim.x + threadIdx.x;   // < B_*NTOT = 90112
    if (i < 2*M_)  g_s[i] = 0.f;
    if (i < B_*T_) out[i] = 0.f;
    if (i < NTOT)  g_W2[i] = (i < H1_) ? W21[i] : W22[i - H1_];
    int n = i % NTOT;   // seed bias: g_c[b][n] = b11[n] | b12[n-768]
    g_c[i] = (n < H1_) ? b11[n] : b12[n - H1_];
}

// ---------------------------------------------------------------------------
// Mega-kernel: [0,176) precompute_c partials, [176,1232) convert B,
//              [1232, ...) convert A. Compute-bound precompute overlaps the
//              memory-bound converts inside one launch.
__global__ __launch_bounds__(256)
void mega_prep_kernel(const float* __restrict__ text,
                      const float* __restrict__ anp,
                      const float* __restrict__ ts,
                      const float* __restrict__ W11,
                      const float* __restrict__ W12) {
    __shared__ float Wsm[48*128];   // 24KB (max kc=48)
    __shared__ float Xsm[64*48];    // 12KB
    const int bid = blockIdx.x;
    const int tid = threadIdx.x;

    if (bid < PRE_BLOCKS) {
        // ---- precompute_c: g_c[b][n] += sum_k X[b][k] * Wlower[k][n] ----
        const int nc = bid / KSPL, ky = bid % KSPL;
        const int n0 = nc * 128;
        const bool sg0 = (nc < 6);
        const int K   = sg0 ? T_ : A_;
        const int kc  = K / KSPL;                  // 48 or 32
        const int k0  = ky * kc;
        const int wst = sg0 ? H1_ : H2_;
        const float* Wrow = sg0 ? (W11 + (size_t)(T_ + k0)*H1_ + n0)
                                : (W12 + (size_t)(T_ + k0)*H2_ + (n0 - H1_));
        const float* X   = sg0 ? text : anp;
        const int xst    = sg0 ? T_ : A_;

        for (int i = tid; i < kc*128; i += 256) {
            int k = i >> 7, n = i & 127;
            Wsm[i] = Wrow[(size_t)k*wst + n];
        }
        for (int i = tid; i < 64*kc; i += 256) {
            int b = i / kc, k = i - b*kc;
            Xsm[b*kc + k] = X[b*xst + k0 + k];
        }
        __syncthreads();

        const int ng = tid & 15, bq = tid >> 4;
        float acc[4][8];
        #pragma unroll
        for (int j = 0; j < 4; j++)
            #pragma unroll
            for (int i = 0; i < 8; i++) acc[j][i] = 0.f;

        for (int k = 0; k < kc; k++) {
            float4 wa = *(const float4*)&Wsm[k*128 + ng*8];
            float4 wb = *(const float4*)&Wsm[k*128 + ng*8 + 4];
            #pragma unroll
            for (int j = 0; j < 4; j++) {
                float x = Xsm[(bq*4 + j)*kc + k];
                acc[j][0] = fmaf(x, wa.x, acc[j][0]);
                acc[j][1] = fmaf(x, wa.y, acc[j][1]);
                acc[j][2] = fmaf(x, wa.z, acc[j][2]);
                acc[j][3] = fmaf(x, wa.w, acc[j][3]);
                acc[j][4] = fmaf(x, wb.x, acc[j][4]);
                acc[j][5] = fmaf(x, wb.y, acc[j][5]);
                acc[j][6] = fmaf(x, wb.z, acc[j][6]);
                acc[j][7] = fmaf(x, wb.w, acc[j][7]);
            }
        }
        #pragma unroll
        for (int j = 0; j < 4; j++)
            #pragma unroll
            for (int i = 0; i < 8; i++)
                atomicAdd(&g_c[(size_t)(bq*4 + j)*NTOT + n0 + ng*8 + i], acc[j][i]);
    } else if (bid < PRE_BLOCKS + CVTB_BLOCKS) {
        // ---- convert B: g_Bh[k][n] = fp16(W11|W12) ----
        int i = (bid - PRE_BLOCKS)*256 + tid;       // < T_*NTOT/4 exactly
        int k  = i / (NTOT/4);
        int n4 = (i % (NTOT/4)) * 4;
        float4 v;
        if (n4 < H1_) v = *(const float4*)(W11 + (size_t)k*H1_ + n4);
        else          v = *(const float4*)(W12 + (size_t)k*H2_ + (n4 - H1_));
        union { __half2 h[2]; uint2 u; } t;
        t.h[0] = __floats2half2_rn(v.x, v.y);
        t.h[1] = __floats2half2_rn(v.z, v.w);
        ((uint2*)g_Bh)[i] = t.u;
    } else {
        // ---- convert A: text_seq fp32 -> fp16 ----
        size_t i = (size_t)(bid - PRE_BLOCKS - CVTB_BLOCKS)*256 + tid;
        float4 v = ((const float4*)ts)[i];
        union { __half2 h[2]; uint2 u; } t;
        t.h[0] = __floats2half2_rn(v.x, v.y);
        t.h[1] = __floats2half2_rn(v.z, v.w);
        ((uint2*)g_Ah)[i] = t.u;
    }
}

// ---------------------------------------------------------------------------
// Fused fp16 mma.sync GEMM + bias + tanh + W2-dot + score accumulation.
// CTA tile 128(M) x 128(N) x 768(K); 8 warps as 4(M) x 2(N), warp tile 32x64.
__global__ __launch_bounds__(256, 2)
void fused_score_mma() {
    extern __shared__ __align__(1024) char smem[];
    const uint32_t sb = s2u(smem);
    const int tid  = threadIdx.x;
    const int lane = tid & 31;
    const int wid  = tid >> 5;
    const int warp_m = wid & 3;    // 0..3  -> m offset 32*warp_m
    const int warp_n = wid >> 2;   // 0..1  -> n offset 64*warp_n

    const int n0 = blockIdx.x * BN;   // x fastest: N tiles share A panel via L2
    const int m0 = blockIdx.y * BM;
    const int seg = (n0 >= H1_) ? 1 : 0;

    float cr[2][8][4];
    #pragma unroll
    for (int mi = 0; mi < 2; mi++)
        #pragma unroll
        for (int ni = 0; ni < 8; ni++)
            #pragma unroll
            for (int r = 0; r < 4; r++) cr[mi][ni][r] = 0.f;

    auto load_stage = [&](int buf, int ks) {
        const uint32_t sA = sb + buf*STAGE_BYTES;
        const uint32_t sB = sA + A_STAGE;
        #pragma unroll
        for (int j = 0; j < 4; j++) {
            int i = tid + 256*j;
            int row = i >> 3, c8 = i & 7;
            cp16(sA + SWZA(row*128 + c8*16),
                 g_Ah + (size_t)(m0 + row)*T_ + ks*BK + c8*8);
        }
        #pragma unroll
        for (int j = 0; j < 4; j++) {
            int i = tid + 256*j;
            int k = i >> 4, n16 = i & 15;
            cp16(sB + SWZB(k*256 + n16*16),
                 g_Bh + (size_t)(ks*BK + k)*NTOT + n0 + n16*8);
        }
    };

    auto compute_stage = [&](int buf) {
        const uint32_t sA = sb + buf*STAGE_BYTES;
        const uint32_t sB = sA + A_STAGE;
        #pragma unroll
        for (int kk = 0; kk < 4; kk++) {            // four k16 steps
            uint32_t af[2][4];
            #pragma unroll
            for (int mi = 0; mi < 2; mi++) {
                int m_l = warp_m*32 + mi*16 + (lane & 15);
                int kc  = kk*16 + (lane >> 4)*8;
                LDSM_X4(af[mi], sA + SWZA(m_l*128 + kc*2));
            }
            uint32_t bf[8][2];
            #pragma unroll
            for (int nj = 0; nj < 4; nj++) {
                int k = kk*16 + ((lane >> 3) & 1)*8 + (lane & 7);
                int n = warp_n*64 + nj*16 + (lane >> 4)*8;
                uint32_t r0, r1, r2, r3;
                LDSM_X4T(r0, r1, r2, r3, sB + SWZB(k*256 + n*2));
                bf[nj*2  ][0] = r0; bf[nj*2  ][1] = r1;
                bf[nj*2+1][0] = r2; bf[nj*2+1][1] = r3;
            }
            #pragma unroll
            for (int mi = 0; mi < 2; mi++)
                #pragma unroll
                for (int ni = 0; ni < 8; ni++)
                    MMA16816(cr[mi][ni], af[mi], bf[ni]);
        }
    };

    // prologue: stages 0..1
    #pragma unroll
    for (int s = 0; s < STG-1; s++) { load_stage(s, s); CP_COMMIT(); }

    #pragma unroll 1
    for (int ks = 0; ks < NKS; ks++) {
        CP_WAIT1();
        __syncthreads();
        int ld = ks + STG - 1;
        if (ld < NKS) load_stage(ld % STG, ld);
        CP_COMMIT();
        compute_stage(ks % STG);
    }

    // ---- epilogue: stage bias tile + W2 in smem (reuse pipeline smem) ----
    __syncthreads();
    float* c_s  = (float*)smem;            // [64][128]
    float* w2_s = c_s + 64*128;
    for (int i = tid; i < 64*128; i += 256) {
        int b = i >> 7, n = i & 127;
        c_s[i] = g_c[(size_t)b*NTOT + n0 + n];
    }
    if (tid < 128) w2_s[tid] = g_W2[n0 + tid];
    __syncthreads();

    float p[4];
    #pragma unroll
    for (int mi = 0; mi < 2; mi++) {
        #pragma unroll
        for (int hf = 0; hf < 2; hf++) {
            int r  = warp_m*32 + mi*16 + hf*8 + (lane >> 2);
            int bb = r & 63;                       // m0 multiple of 128, B=64
            const float* crow = c_s + bb*128;
            float acc = 0.f;
            #pragma unroll
            for (int ni = 0; ni < 8; ni++) {
                int cc = warp_n*64 + ni*8 + (lane & 3)*2;
                float u0 = cr[mi][ni][hf*2+0] + crow[cc];
                float u1 = cr[mi][ni][hf*2+1] + crow[cc+1];
                acc += tanhf(u0)*w2_s[cc] + tanhf(u1)*w2_s[cc+1];
            }
            p[mi*2 + hf] = acc;
        }
    }
    #pragma unroll
    for (int i = 0; i < 4; i++) {
        p[i] += __shfl_xor_sync(0xffffffffu, p[i], 1);
        p[i] += __shfl_xor_sync(0xffffffffu, p[i], 2);
    }
    if ((lane & 3) == 0) {
        #pragma unroll
        for (int mi = 0; mi < 2; mi++)
            #pragma unroll
            for (int hf = 0; hf < 2; hf++) {
                int m = m0 + warp_m*32 + mi*16 + hf*8 + (lane >> 2);
                // transposed score layout: [seg][b][s]
                atomicAdd(&g_s[seg*M_ + (m & 63)*S_ + (m >> 6)], p[mi*2 + hf]);
            }
    }
}

// ---------------------------------------------------------------------------
// softmax over S per batch for both branches (warp-shuffle two-level reduce)
__global__ void softmax_combine_kernel() {
    __shared__ float sred[2][16];
    const int b = blockIdx.x;
    const int s = threadIdx.x;      // 512
    const int lane = s & 31, wrp = s >> 5;

    float v1 = g_s[b*S_ + s];
    float v2 = g_s[M_ + b*S_ + s];

    // max reduce (both branches together)
    float m1 = v1, m2 = v2;
    #pragma unroll
    for (int o = 16; o > 0; o >>= 1) {
        m1 = fmaxf(m1, __shfl_xor_sync(0xffffffffu, m1, o));
        m2 = fmaxf(m2, __shfl_xor_sync(0xffffffffu, m2, o));
    }
    if (lane == 0) { sred[0][wrp] = m1; sred[1][wrp] = m2; }
    __syncthreads();
    if (s < 32) {
        float a = sred[0][lane & 15], c = sred[1][lane & 15];
        #pragma unroll
        for (int o = 8; o > 0; o >>= 1) {
            a = fmaxf(a, __shfl_xor_sync(0xffffffffu, a, o));
            c = fmaxf(c, __shfl_xor_sync(0xffffffffu, c, o));
        }
        if (lane == 0) { sred[0][0] = a; sred[1][0] = c; }
    }
    __syncthreads();
    m1 = sred[0][0]; m2 = sred[1][0];
    __syncthreads();

    float e1 = expf(v1 - m1), e2 = expf(v2 - m2);
    float s1 = e1, s2 = e2;
    #pragma unroll
    for (int o = 16; o > 0; o >>= 1) {
        s1 += __shfl_xor_sync(0xffffffffu, s1, o);
        s2 += __shfl_xor_sync(0xffffffffu, s2, o);
    }
    if (lane == 0) { sred[0][wrp] = s1; sred[1][wrp] = s2; }
    __syncthreads();
    if (s < 32) {
        float a = sred[0][lane & 15], c = sred[1][lane & 15];
        #pragma unroll
        for (int o = 8; o > 0; o >>= 1) {
            a += __shfl_xor_sync(0xffffffffu, a, o);
            c += __shfl_xor_sync(0xffffffffu, c, o);
        }
        if (lane == 0) { sred[0][0] = a; sred[1][0] = c; }
    }
    __syncthreads();
    s1 = sred[0][0]; s2 = sred[1][0];

    g_w[b*S_ + s] = (e1/s1 + e2/s2) * (0.5f / (float)S_);
}

// ---------------------------------------------------------------------------
// out[b,t] += sum_{s in chunk} g_w[b][s] * text_seq[s,b,t]   (split-S x4)
__global__ void weighted_sum_kernel(const float* __restrict__ ts,
                                    float* __restrict__ out) {
    __shared__ float ws[S_/SSPLIT];
    const int b  = blockIdx.y;
    const int sz = blockIdx.z;
    const int sbeg = sz * (S_/SSPLIT);
    const int t = blockIdx.x * blockDim.x + threadIdx.x;
    for (int i = threadIdx.x; i < S_/SSPLIT; i += blockDim.x)
        ws[i] = g_w[b*S_ + sbeg + i];
    __syncthreads();
    float acc = 0.f;
    const float* p = ts + (size_t)sbeg * B_ * T_ + (size_t)b * T_ + t;
    #pragma unroll 8
    for (int s = 0; s < S_/SSPLIT; s++)
        acc = fmaf(ws[s], p[(size_t)s * B_ * T_], acc);
    atomicAdd(&out[b*T_ + t], acc);
}

// ---------------------------------------------------------------------------
extern "C" void kernel_launch(void* const* d_in, const int* in_sizes, int n_in,
                              void* d_out, int out_size) {
    const float* text = (const float*)d_in[0];
    const float* anp  = (const float*)d_in[1];
    const float* ts   = (const float*)d_in[2];
    const float* W11  = (const float*)d_in[3];
    const float* b11  = (const float*)d_in[4];
    const float* W21  = (const float*)d_in[5];
    // d_in[6] = b21 (softmax shift-invariant -> unused)
    const float* W12  = (const float*)d_in[7];
    const float* b12  = (const float*)d_in[8];
    const float* W22  = (const float*)d_in[9];
    // d_in[10] = b22 (unused)
    (void)in_sizes; (void)n_in; (void)out_size;

    cudaFuncSetAttribute(fused_score_mma,
                         cudaFuncAttributeMaxDynamicSharedMemorySize, SMEM_DYN);

    init_misc_kernel<<<B_*NTOT/256, 256>>>(b11, b12, W21, W22, (float*)d_out);

    mega_prep_kernel<<<MEGA_BLOCKS, 256>>>(text, anp, ts, W11, W12);

    dim3 g1(NTOT/BN, M_/BM);   // (11, 256), N-tiles fastest -> A reuse in L2
    fused_score_mma<<<g1, 256, SMEM_DYN>>>();

    softmax_combine_kernel<<<B_, S_>>>();

    dim3 g2(T_/256, B_, SSPLIT);
    weighted_sum_kernel<<<g2, 256>>>(ts, (float*)d_out);
}